// round 2
// baseline (speedup 1.0000x reference)
#include <cuda_runtime.h>
#include <cuda_fp16.h>
#include <cstdint>

#define N_NODES 8192
#define F_DIM   128
#define ALPHA   0.2f

// ---------------- scratch (device globals; no allocations allowed) ----------
__device__ float  g_es[N_NODES];
__device__ float  g_ed[N_NODES];
__device__ float  g_maxed;
__device__ __half g_WhT[(size_t)F_DIM * N_NODES];   // [f][node]  (transposed Wh, fp16)

// ---------------- helpers ----------------------------------------------------
__device__ __forceinline__ uint32_t packh2(float x, float y) {
    __half2 h = __floats2half2_rn(x, y);
    return reinterpret_cast<uint32_t&>(h);
}

__device__ __forceinline__ void mma16816(float* c,
                                         uint32_t a0, uint32_t a1, uint32_t a2, uint32_t a3,
                                         uint32_t b0, uint32_t b1) {
    asm volatile(
        "mma.sync.aligned.m16n8k16.row.col.f32.f16.f16.f32 "
        "{%0,%1,%2,%3}, {%4,%5,%6,%7}, {%8,%9}, {%0,%1,%2,%3};\n"
        : "+f"(c[0]), "+f"(c[1]), "+f"(c[2]), "+f"(c[3])
        : "r"(a0), "r"(a1), "r"(a2), "r"(a3), "r"(b0), "r"(b1));
}

__device__ __forceinline__ void cp16(void* s, const void* g) {
    unsigned sa = (unsigned)__cvta_generic_to_shared(s);
    asm volatile("cp.async.cg.shared.global [%0], [%1], 16;\n" :: "r"(sa), "l"(g));
}
__device__ __forceinline__ void cp_commit() { asm volatile("cp.async.commit_group;\n"); }
__device__ __forceinline__ void cp_wait1()  { asm volatile("cp.async.wait_group 1;\n"); }

__device__ __forceinline__ float leakyf(float x) { return fmaxf(x, ALPHA * x); }

__device__ __forceinline__ float pcalc(int aj, float e, float m) {
    float x = leakyf(e);
    return aj ? __expf(x - m) : 0.f;
}

// ---------------- kernel 1: Wh = h@W (fp32), write WhT fp16, es, ed ----------
__global__ void __launch_bounds__(256) k_wh(const float* __restrict__ h,
                                            const float* __restrict__ Wm,
                                            const float* __restrict__ a) {
    // phase-1 union: sW[32][128] (16384B) + sH[64][33] (8448B) = 24832B
    // phase-2:       sWh[64][132]                              = 33792B
    __shared__ __align__(16) char sbuf[64 * 132 * 4];
    __shared__ float sWa1[F_DIM], sWa2[F_DIM];

    float (*sW)[128] = reinterpret_cast<float(*)[128]>(sbuf);
    float (*sH)[33]  = reinterpret_cast<float(*)[33]>(sbuf + 16384);
    float (*sWh)[132] = reinterpret_cast<float(*)[132]>(sbuf);

    const int t  = threadIdx.x;
    const int tx = t & 31;
    const int ty = t >> 5;
    const int i0 = blockIdx.x * 64;

    if (t < F_DIM) { sWa1[t] = a[t]; sWa2[t] = a[F_DIM + t]; }

    float acc[8][4];
#pragma unroll
    for (int r = 0; r < 8; ++r)
#pragma unroll
        for (int c = 0; c < 4; ++c) acc[r][c] = 0.f;

    for (int kb = 0; kb < 4; ++kb) {
        const int k0 = kb * 32;
        __syncthreads();
        // W tile: 32 x 128
#pragma unroll
        for (int m = 0; m < 16; ++m) {
            int idx = t + m * 256;
            int r = idx >> 7, c = idx & 127;
            sW[r][c] = Wm[(k0 + r) * F_DIM + c];
        }
        // h tile: 64 x 32
#pragma unroll
        for (int m = 0; m < 8; ++m) {
            int idx = t + m * 256;
            int r = idx >> 5, c = idx & 31;
            sH[r][c] = h[(size_t)(i0 + r) * F_DIM + k0 + c];
        }
        __syncthreads();
#pragma unroll 4
        for (int kk = 0; kk < 32; ++kk) {
            float4 bv = *(const float4*)&sW[kk][tx * 4];
#pragma unroll
            for (int rr = 0; rr < 8; ++rr) {
                float av = sH[ty * 8 + rr][kk];
                acc[rr][0] += av * bv.x;
                acc[rr][1] += av * bv.y;
                acc[rr][2] += av * bv.z;
                acc[rr][3] += av * bv.w;
            }
        }
    }
    __syncthreads();
#pragma unroll
    for (int rr = 0; rr < 8; ++rr) {
        *(float4*)&sWh[ty * 8 + rr][tx * 4] =
            make_float4(acc[rr][0], acc[rr][1], acc[rr][2], acc[rr][3]);
    }
    __syncthreads();

    // es / ed : warp ty owns rows ty*8 .. ty*8+7  (dot Wh row with a1 / a2)
#pragma unroll
    for (int rr = 0; rr < 8; ++rr) {
        int r = ty * 8 + rr;
        float4 v = *(const float4*)&sWh[r][tx * 4];
        float s1 = v.x * sWa1[tx * 4] + v.y * sWa1[tx * 4 + 1] +
                   v.z * sWa1[tx * 4 + 2] + v.w * sWa1[tx * 4 + 3];
        float s2 = v.x * sWa2[tx * 4] + v.y * sWa2[tx * 4 + 1] +
                   v.z * sWa2[tx * 4 + 2] + v.w * sWa2[tx * 4 + 3];
#pragma unroll
        for (int off = 16; off; off >>= 1) {
            s1 += __shfl_xor_sync(0xffffffffu, s1, off);
            s2 += __shfl_xor_sync(0xffffffffu, s2, off);
        }
        if (tx == 0) { g_es[i0 + r] = s1; g_ed[i0 + r] = s2; }
    }

    // WhT fp16: thread t -> feature c = t/2, rows (t&1)*32 .. +31
    {
        int c = t >> 1, roff = (t & 1) * 32;
#pragma unroll 8
        for (int i = 0; i < 32; ++i) {
            int r = roff + i;
            g_WhT[(size_t)c * N_NODES + i0 + r] = __float2half(sWh[r][c]);
        }
    }
}

// ---------------- kernel 2: global max of ed ---------------------------------
__global__ void k_max() {
    __shared__ float red[256];
    int t = threadIdx.x;
    float m = -1e30f;
    for (int i = t; i < N_NODES; i += 256) m = fmaxf(m, g_ed[i]);
    red[t] = m;
    __syncthreads();
#pragma unroll
    for (int s = 128; s; s >>= 1) {
        if (t < s) red[t] = fmaxf(red[t], red[t + s]);
        __syncthreads();
    }
    if (t == 0) g_maxed = red[0];
}

// ---------------- kernel 3: fused masked-softmax attention @ Wh --------------
// grid: 128 CTAs (64 rows each), 256 threads (8 warps: 4 row-groups x 2 K-halves)
#define BM 64
#define BN 128
#define NJ (N_NODES / BN)
#define ADJ_PB 544           // bytes/row  (136 ints)
#define WHT_PH 136           // halfs/row  (272 bytes)
#define ADJ_TILE (64 * ADJ_PB)      // 34816
#define WHT_TILE (128 * WHT_PH * 2) // 34816
#define OFF_A0 0
#define OFF_A1 (OFF_A0 + ADJ_TILE)
#define OFF_W0 (OFF_A1 + ADJ_TILE)
#define OFF_W1 (OFF_W0 + WHT_TILE)
#define OFF_E0 (OFF_W1 + WHT_TILE)
#define OFF_E1 (OFF_E0 + 512)
#define SMEM_FLASH (OFF_E1 + 512)   // 140288

__global__ void __launch_bounds__(256, 1) k_flash(const int* __restrict__ adj,
                                                  float* __restrict__ out) {
    extern __shared__ __align__(16) char sm[];
    const int t = threadIdx.x;
    const int l = t & 31;
    const int w = t >> 5;
    const int rg = w & 3;    // row group (16 rows)
    const int kh = w >> 2;   // K half (j cols kh*64 .. +63 of tile)
    const int i0 = blockIdx.x * BM;

    const int row0 = rg * 16 + (l >> 2);
    const int row1 = row0 + 8;

    const float maxed = g_maxed;
    const float es0 = g_es[i0 + row0];
    const float es1 = g_es[i0 + row1];
    const float m0 = leakyf(es0 + maxed);
    const float m1 = leakyf(es1 + maxed);

    float acc[16][4];
#pragma unroll
    for (int n = 0; n < 16; ++n)
#pragma unroll
        for (int i = 0; i < 4; ++i) acc[n][i] = 0.f;
    float ls0 = 0.f, ls1 = 0.f;

    // ---- async tile loader ----
    auto issue = [&](int buf, int jb) {
        const int j0 = jb * BN;
        char* A  = sm + (buf ? OFF_A1 : OFF_A0);
        char* Wt = sm + (buf ? OFF_W1 : OFF_W0);
        char* E  = sm + (buf ? OFF_E1 : OFF_E0);
#pragma unroll
        for (int m = 0; m < 8; ++m) {               // adj 64 x 128 ints
            int c = t + m * 256;
            int r = c >> 5, cc = c & 31;
            cp16(A + r * ADJ_PB + cc * 16, adj + (size_t)(i0 + r) * N_NODES + j0 + cc * 4);
        }
#pragma unroll
        for (int m = 0; m < 8; ++m) {               // WhT 128 x 128 halfs
            int c = t + m * 256;
            int r = c >> 4, cc = c & 15;
            cp16(Wt + r * (WHT_PH * 2) + cc * 16, g_WhT + (size_t)r * N_NODES + j0 + cc * 8);
        }
        if (t < 32) cp16(E + t * 16, g_ed + j0 + t * 4);   // ed tile (128 f32)
    };

    issue(0, 0);
    cp_commit();

    for (int jb = 0; jb < NJ; ++jb) {
        const int buf = jb & 1;
        __syncthreads();                 // prev compute done before refilling buf^1
        if (jb + 1 < NJ) issue(buf ^ 1, jb + 1);
        cp_commit();
        cp_wait1();
        __syncthreads();

        const char*  A  = sm + (buf ? OFF_A1 : OFF_A0);
        const __half* Wt = (const __half*)(sm + (buf ? OFF_W1 : OFF_W0));
        const float* E  = (const float*)(sm + (buf ? OFF_E1 : OFF_E0));
        const int* ar0 = (const int*)(A + row0 * ADJ_PB);
        const int* ar1 = (const int*)(A + row1 * ADJ_PB);

#pragma unroll
        for (int ktl = 0; ktl < 4; ++ktl) {
            const int c0 = kh * 64 + ktl * 16 + (l & 3) * 2;
            float e0 = E[c0], e1 = E[c0 + 1], e8 = E[c0 + 8], e9 = E[c0 + 9];
            int2 q00 = *(const int2*)&ar0[c0];
            int2 q08 = *(const int2*)&ar0[c0 + 8];
            int2 q10 = *(const int2*)&ar1[c0];
            int2 q18 = *(const int2*)&ar1[c0 + 8];

            float p00 = pcalc(q00.x, es0 + e0, m0);
            float p01 = pcalc(q00.y, es0 + e1, m0);
            float p08 = pcalc(q08.x, es0 + e8, m0);
            float p09 = pcalc(q08.y, es0 + e9, m0);
            float p10 = pcalc(q10.x, es1 + e0, m1);
            float p11 = pcalc(q10.y, es1 + e1, m1);
            float p18 = pcalc(q18.x, es1 + e8, m1);
            float p19 = pcalc(q18.y, es1 + e9, m1);

            ls0 += (p00 + p01) + (p08 + p09);
            ls1 += (p10 + p11) + (p18 + p19);

            uint32_t a0 = packh2(p00, p01);
            uint32_t a1 = packh2(p10, p11);
            uint32_t a2 = packh2(p08, p09);
            uint32_t a3 = packh2(p18, p19);

            const __half* bbase = Wt + (size_t)(l >> 2) * WHT_PH + c0;
#pragma unroll
            for (int nt = 0; nt < 16; ++nt) {
                const __half* bp = bbase + nt * 8 * WHT_PH;
                uint32_t b0 = *(const uint32_t*)bp;
                uint32_t b1 = *(const uint32_t*)(bp + 8);
                mma16816(acc[nt], a0, a1, a2, a3, b0, b1);
            }
        }
    }

    // quad-reduce row sums (lanes sharing l>>2)
    ls0 += __shfl_xor_sync(0xffffffffu, ls0, 1);
    ls0 += __shfl_xor_sync(0xffffffffu, ls0, 2);
    ls1 += __shfl_xor_sync(0xffffffffu, ls1, 1);
    ls1 += __shfl_xor_sync(0xffffffffu, ls1, 2);

    __syncthreads();
    float* mrg  = (float*)sm;                 // 4 warps * 2048 f = 32KB (in adj area)
    float* mrgL = (float*)(sm + OFF_E0);      // 512B

    if (kh == 1) {
#pragma unroll
        for (int nt = 0; nt < 16; ++nt)
            *(float4*)&mrg[rg * 2048 + nt * 128 + l * 4] =
                make_float4(acc[nt][0], acc[nt][1], acc[nt][2], acc[nt][3]);
        if ((l & 3) == 0) {
            mrgL[rg * 32 + (l >> 2) * 2]     = ls0;
            mrgL[rg * 32 + (l >> 2) * 2 + 1] = ls1;
        }
    }
    __syncthreads();
    if (kh == 0) {
        ls0 += mrgL[rg * 32 + (l >> 2) * 2];
        ls1 += mrgL[rg * 32 + (l >> 2) * 2 + 1];
        float inv0 = 1.f / ls0;
        float inv1 = 1.f / ls1;
#pragma unroll
        for (int nt = 0; nt < 16; ++nt) {
            float4 p = *(const float4*)&mrg[rg * 2048 + nt * 128 + l * 4];
            float o0 = (acc[nt][0] + p.x) * inv0;
            float o1 = (acc[nt][1] + p.y) * inv0;
            float o2 = (acc[nt][2] + p.z) * inv1;
            float o3 = (acc[nt][3] + p.w) * inv1;
            int col = nt * 8 + (l & 3) * 2;
            *(float2*)&out[(size_t)(i0 + row0) * F_DIM + col] = make_float2(o0, o1);
            *(float2*)&out[(size_t)(i0 + row1) * F_DIM + col] = make_float2(o2, o3);
        }
    }
}

// ---------------- launcher ---------------------------------------------------
extern "C" void kernel_launch(void* const* d_in, const int* in_sizes, int n_in,
                              void* d_out, int out_size) {
    const float* h   = (const float*)d_in[0];
    const int*   adj = (const int*)d_in[1];
    const float* W   = (const float*)d_in[2];
    const float* a   = (const float*)d_in[3];
    float* out = (float*)d_out;

    k_wh<<<N_NODES / 64, 256>>>(h, W, a);
    k_max<<<1, 256>>>();

    cudaFuncSetAttribute(k_flash, cudaFuncAttributeMaxDynamicSharedMemorySize, SMEM_FLASH);
    k_flash<<<N_NODES / BM, 256, SMEM_FLASH>>>(adj, out);
}

// round 3
// speedup vs baseline: 1.0050x; 1.0050x over previous
#include <cuda_runtime.h>
#include <cuda_fp16.h>
#include <cstdint>

#define N_NODES 8192
#define F_DIM   128
#define ALPHA   0.2f

// ---------------- scratch (device globals; no allocations allowed) ----------
__device__ float  g_es[N_NODES];
__device__ float  g_ed[N_NODES];
__device__ float  g_maxed;
__device__ __half g_WhT[(size_t)F_DIM * N_NODES];   // [f][node]  (transposed Wh, fp16)

// ---------------- helpers ----------------------------------------------------
__device__ __forceinline__ uint32_t packh2(float x, float y) {
    __half2 h = __floats2half2_rn(x, y);
    return reinterpret_cast<uint32_t&>(h);
}

__device__ __forceinline__ void mma16816(float* c,
                                         uint32_t a0, uint32_t a1, uint32_t a2, uint32_t a3,
                                         uint32_t b0, uint32_t b1) {
    asm volatile(
        "mma.sync.aligned.m16n8k16.row.col.f32.f16.f16.f32 "
        "{%0,%1,%2,%3}, {%4,%5,%6,%7}, {%8,%9}, {%0,%1,%2,%3};\n"
        : "+f"(c[0]), "+f"(c[1]), "+f"(c[2]), "+f"(c[3])
        : "r"(a0), "r"(a1), "r"(a2), "r"(a3), "r"(b0), "r"(b1));
}

__device__ __forceinline__ void cp16(void* s, const void* g) {
    unsigned sa = (unsigned)__cvta_generic_to_shared(s);
    asm volatile("cp.async.cg.shared.global [%0], [%1], 16;\n" :: "r"(sa), "l"(g));
}
__device__ __forceinline__ void cp_commit() { asm volatile("cp.async.commit_group;\n"); }
__device__ __forceinline__ void cp_wait1()  { asm volatile("cp.async.wait_group 1;\n"); }

__device__ __forceinline__ float leakyf(float x) { return fmaxf(x, ALPHA * x); }

__device__ __forceinline__ float pcalc(int aj, float e, float m) {
    float x = leakyf(e);
    return aj ? __expf(x - m) : 0.f;
}

// ---------------- kernel 1: Wh = h@W (fp32), write WhT fp16, es, ed ----------
__global__ void __launch_bounds__(256) k_wh(const float* __restrict__ h,
                                            const float* __restrict__ Wm,
                                            const float* __restrict__ a) {
    // phase-1 union: sW[32][128] (16384B) + sH[64][33] (8448B) = 24832B
    // phase-2:       sWh[64][132]                              = 33792B
    __shared__ __align__(16) char sbuf[64 * 132 * 4];
    __shared__ float sWa1[F_DIM], sWa2[F_DIM];

    float (*sW)[128] = reinterpret_cast<float(*)[128]>(sbuf);
    float (*sH)[33]  = reinterpret_cast<float(*)[33]>(sbuf + 16384);
    float (*sWh)[132] = reinterpret_cast<float(*)[132]>(sbuf);

    const int t  = threadIdx.x;
    const int tx = t & 31;
    const int ty = t >> 5;
    const int i0 = blockIdx.x * 64;

    if (t < F_DIM) { sWa1[t] = a[t]; sWa2[t] = a[F_DIM + t]; }

    float acc[8][4];
#pragma unroll
    for (int r = 0; r < 8; ++r)
#pragma unroll
        for (int c = 0; c < 4; ++c) acc[r][c] = 0.f;

    for (int kb = 0; kb < 4; ++kb) {
        const int k0 = kb * 32;
        __syncthreads();
        // W tile: 32 x 128
#pragma unroll
        for (int m = 0; m < 16; ++m) {
            int idx = t + m * 256;
            int r = idx >> 7, c = idx & 127;
            sW[r][c] = Wm[(k0 + r) * F_DIM + c];
        }
        // h tile: 64 x 32
#pragma unroll
        for (int m = 0; m < 8; ++m) {
            int idx = t + m * 256;
            int r = idx >> 5, c = idx & 31;
            sH[r][c] = h[(size_t)(i0 + r) * F_DIM + k0 + c];
        }
        __syncthreads();
#pragma unroll 4
        for (int kk = 0; kk < 32; ++kk) {
            float4 bv = *(const float4*)&sW[kk][tx * 4];
#pragma unroll
            for (int rr = 0; rr < 8; ++rr) {
                float av = sH[ty * 8 + rr][kk];
                acc[rr][0] += av * bv.x;
                acc[rr][1] += av * bv.y;
                acc[rr][2] += av * bv.z;
                acc[rr][3] += av * bv.w;
            }
        }
    }
    __syncthreads();
#pragma unroll
    for (int rr = 0; rr < 8; ++rr) {
        *(float4*)&sWh[ty * 8 + rr][tx * 4] =
            make_float4(acc[rr][0], acc[rr][1], acc[rr][2], acc[rr][3]);
    }
    __syncthreads();

    // es / ed : warp ty owns rows ty*8 .. ty*8+7  (dot Wh row with a1 / a2)
#pragma unroll
    for (int rr = 0; rr < 8; ++rr) {
        int r = ty * 8 + rr;
        float4 v = *(const float4*)&sWh[r][tx * 4];
        float s1 = v.x * sWa1[tx * 4] + v.y * sWa1[tx * 4 + 1] +
                   v.z * sWa1[tx * 4 + 2] + v.w * sWa1[tx * 4 + 3];
        float s2 = v.x * sWa2[tx * 4] + v.y * sWa2[tx * 4 + 1] +
                   v.z * sWa2[tx * 4 + 2] + v.w * sWa2[tx * 4 + 3];
#pragma unroll
        for (int off = 16; off; off >>= 1) {
            s1 += __shfl_xor_sync(0xffffffffu, s1, off);
            s2 += __shfl_xor_sync(0xffffffffu, s2, off);
        }
        if (tx == 0) { g_es[i0 + r] = s1; g_ed[i0 + r] = s2; }
    }

    // WhT fp16: thread t -> feature c = t/2, rows (t&1)*32 .. +31
    {
        int c = t >> 1, roff = (t & 1) * 32;
#pragma unroll 8
        for (int i = 0; i < 32; ++i) {
            int r = roff + i;
            g_WhT[(size_t)c * N_NODES + i0 + r] = __float2half(sWh[r][c]);
        }
    }
}

// ---------------- kernel 2: global max of ed ---------------------------------
__global__ void k_max() {
    __shared__ float red[256];
    int t = threadIdx.x;
    float m = -1e30f;
    for (int i = t; i < N_NODES; i += 256) m = fmaxf(m, g_ed[i]);
    red[t] = m;
    __syncthreads();
#pragma unroll
    for (int s = 128; s; s >>= 1) {
        if (t < s) red[t] = fmaxf(red[t], red[t + s]);
        __syncthreads();
    }
    if (t == 0) g_maxed = red[0];
}

// ---------------- kernel 3: fused masked-softmax attention @ Wh --------------
// grid: 128 CTAs (64 rows each), 256 threads (8 warps: 4 row-groups x 2 K-halves)
#define BM 64
#define BN 128
#define NJ (N_NODES / BN)
#define ADJ_PB 544           // bytes/row  (136 ints)
#define WHT_PH 136           // halfs/row  (272 bytes)
#define ADJ_TILE (64 * ADJ_PB)      // 34816
#define WHT_TILE (128 * WHT_PH * 2) // 34816
#define OFF_A0 0
#define OFF_A1 (OFF_A0 + ADJ_TILE)
#define OFF_W0 (OFF_A1 + ADJ_TILE)
#define OFF_W1 (OFF_W0 + WHT_TILE)
#define OFF_E0 (OFF_W1 + WHT_TILE)
#define OFF_E1 (OFF_E0 + 512)
#define SMEM_FLASH (OFF_E1 + 512)   // 140288

__global__ void __launch_bounds__(256, 1) k_flash(const int* __restrict__ adj,
                                                  float* __restrict__ out) {
    extern __shared__ __align__(16) char sm[];
    const int t = threadIdx.x;
    const int l = t & 31;
    const int w = t >> 5;
    const int rg = w & 3;    // row group (16 rows)
    const int kh = w >> 2;   // K half (j cols kh*64 .. +63 of tile)
    const int i0 = blockIdx.x * BM;

    const int row0 = rg * 16 + (l >> 2);
    const int row1 = row0 + 8;

    const float maxed = g_maxed;
    const float es0 = g_es[i0 + row0];
    const float es1 = g_es[i0 + row1];
    const float m0 = leakyf(es0 + maxed);
    const float m1 = leakyf(es1 + maxed);

    float acc[16][4];
#pragma unroll
    for (int n = 0; n < 16; ++n)
#pragma unroll
        for (int i = 0; i < 4; ++i) acc[n][i] = 0.f;
    float ls0 = 0.f, ls1 = 0.f;

    // ---- async tile loader ----
    auto issue = [&](int buf, int jb) {
        const int j0 = jb * BN;
        char* A  = sm + (buf ? OFF_A1 : OFF_A0);
        char* Wt = sm + (buf ? OFF_W1 : OFF_W0);
        char* E  = sm + (buf ? OFF_E1 : OFF_E0);
#pragma unroll
        for (int m = 0; m < 8; ++m) {               // adj 64 x 128 ints
            int c = t + m * 256;
            int r = c >> 5, cc = c & 31;
            cp16(A + r * ADJ_PB + cc * 16, adj + (size_t)(i0 + r) * N_NODES + j0 + cc * 4);
        }
#pragma unroll
        for (int m = 0; m < 8; ++m) {               // WhT 128 x 128 halfs
            int c = t + m * 256;
            int r = c >> 4, cc = c & 15;
            cp16(Wt + r * (WHT_PH * 2) + cc * 16, g_WhT + (size_t)r * N_NODES + j0 + cc * 8);
        }
        if (t < 32) cp16(E + t * 16, g_ed + j0 + t * 4);   // ed tile (128 f32)
    };

    issue(0, 0);
    cp_commit();

    for (int jb = 0; jb < NJ; ++jb) {
        const int buf = jb & 1;
        __syncthreads();                 // prev compute done before refilling buf^1
        if (jb + 1 < NJ) issue(buf ^ 1, jb + 1);
        cp_commit();
        cp_wait1();
        __syncthreads();

        const char*  A  = sm + (buf ? OFF_A1 : OFF_A0);
        const __half* Wt = (const __half*)(sm + (buf ? OFF_W1 : OFF_W0));
        const float* E  = (const float*)(sm + (buf ? OFF_E1 : OFF_E0));
        const int* ar0 = (const int*)(A + row0 * ADJ_PB);
        const int* ar1 = (const int*)(A + row1 * ADJ_PB);

#pragma unroll
        for (int ktl = 0; ktl < 4; ++ktl) {
            const int c0 = kh * 64 + ktl * 16 + (l & 3) * 2;
            float e0 = E[c0], e1 = E[c0 + 1], e8 = E[c0 + 8], e9 = E[c0 + 9];
            int2 q00 = *(const int2*)&ar0[c0];
            int2 q08 = *(const int2*)&ar0[c0 + 8];
            int2 q10 = *(const int2*)&ar1[c0];
            int2 q18 = *(const int2*)&ar1[c0 + 8];

            float p00 = pcalc(q00.x, es0 + e0, m0);
            float p01 = pcalc(q00.y, es0 + e1, m0);
            float p08 = pcalc(q08.x, es0 + e8, m0);
            float p09 = pcalc(q08.y, es0 + e9, m0);
            float p10 = pcalc(q10.x, es1 + e0, m1);
            float p11 = pcalc(q10.y, es1 + e1, m1);
            float p18 = pcalc(q18.x, es1 + e8, m1);
            float p19 = pcalc(q18.y, es1 + e9, m1);

            ls0 += (p00 + p01) + (p08 + p09);
            ls1 += (p10 + p11) + (p18 + p19);

            uint32_t a0 = packh2(p00, p01);
            uint32_t a1 = packh2(p10, p11);
            uint32_t a2 = packh2(p08, p09);
            uint32_t a3 = packh2(p18, p19);

            const __half* bbase = Wt + (size_t)(l >> 2) * WHT_PH + c0;
#pragma unroll
            for (int nt = 0; nt < 16; ++nt) {
                const __half* bp = bbase + nt * 8 * WHT_PH;
                uint32_t b0 = *(const uint32_t*)bp;
                uint32_t b1 = *(const uint32_t*)(bp + 8);
                mma16816(acc[nt], a0, a1, a2, a3, b0, b1);
            }
        }
    }

    // quad-reduce row sums (lanes sharing l>>2)
    ls0 += __shfl_xor_sync(0xffffffffu, ls0, 1);
    ls0 += __shfl_xor_sync(0xffffffffu, ls0, 2);
    ls1 += __shfl_xor_sync(0xffffffffu, ls1, 1);
    ls1 += __shfl_xor_sync(0xffffffffu, ls1, 2);

    __syncthreads();
    float* mrg  = (float*)sm;                 // 4 warps * 2048 f = 32KB (in adj area)
    float* mrgL = (float*)(sm + OFF_E0);      // 512B

    if (kh == 1) {
#pragma unroll
        for (int nt = 0; nt < 16; ++nt)
            *(float4*)&mrg[rg * 2048 + nt * 128 + l * 4] =
                make_float4(acc[nt][0], acc[nt][1], acc[nt][2], acc[nt][3]);
        if ((l & 3) == 0) {
            mrgL[rg * 32 + (l >> 2) * 2]     = ls0;
            mrgL[rg * 32 + (l >> 2) * 2 + 1] = ls1;
        }
    }
    __syncthreads();
    if (kh == 0) {
        ls0 += mrgL[rg * 32 + (l >> 2) * 2];
        ls1 += mrgL[rg * 32 + (l >> 2) * 2 + 1];
        float inv0 = 1.f / ls0;
        float inv1 = 1.f / ls1;
#pragma unroll
        for (int nt = 0; nt < 16; ++nt) {
            float4 p = *(const float4*)&mrg[rg * 2048 + nt * 128 + l * 4];
            float o0 = (acc[nt][0] + p.x) * inv0;
            float o1 = (acc[nt][1] + p.y) * inv0;
            float o2 = (acc[nt][2] + p.z) * inv1;
            float o3 = (acc[nt][3] + p.w) * inv1;
            int col = nt * 8 + (l & 3) * 2;
            *(float2*)&out[(size_t)(i0 + row0) * F_DIM + col] = make_float2(o0, o1);
            *(float2*)&out[(size_t)(i0 + row1) * F_DIM + col] = make_float2(o2, o3);
        }
    }
}

// ---------------- launcher ---------------------------------------------------
extern "C" void kernel_launch(void* const* d_in, const int* in_sizes, int n_in,
                              void* d_out, int out_size) {
    const float* h   = (const float*)d_in[0];
    const int*   adj = (const int*)d_in[1];
    const float* W   = (const float*)d_in[2];
    const float* a   = (const float*)d_in[3];
    float* out = (float*)d_out;

    k_wh<<<N_NODES / 64, 256>>>(h, W, a);
    k_max<<<1, 256>>>();

    cudaFuncSetAttribute(k_flash, cudaFuncAttributeMaxDynamicSharedMemorySize, SMEM_FLASH);
    k_flash<<<N_NODES / BM, 256, SMEM_FLASH>>>(adj, out);
}

// round 4
// speedup vs baseline: 1.0085x; 1.0034x over previous
#include <cuda_runtime.h>
#include <cuda_fp16.h>
#include <cstdint>

#define N_NODES 8192
#define F_DIM   128
#define ALPHA   0.2f

// ---------------- scratch (device globals; no allocations allowed) ----------
__device__ float  g_es[N_NODES];
__device__ float  g_ed[N_NODES];
__device__ float  g_maxed;
__device__ __half g_WhT[(size_t)F_DIM * N_NODES];   // [f][node]  (transposed Wh, fp16)

// ---------------- helpers ----------------------------------------------------
__device__ __forceinline__ uint32_t packh2(float x, float y) {
    __half2 h = __floats2half2_rn(x, y);
    return reinterpret_cast<uint32_t&>(h);
}

__device__ __forceinline__ void mma16816(float* c,
                                         uint32_t a0, uint32_t a1, uint32_t a2, uint32_t a3,
                                         uint32_t b0, uint32_t b1) {
    asm volatile(
        "mma.sync.aligned.m16n8k16.row.col.f32.f16.f16.f32 "
        "{%0,%1,%2,%3}, {%4,%5,%6,%7}, {%8,%9}, {%0,%1,%2,%3};\n"
        : "+f"(c[0]), "+f"(c[1]), "+f"(c[2]), "+f"(c[3])
        : "r"(a0), "r"(a1), "r"(a2), "r"(a3), "r"(b0), "r"(b1));
}

__device__ __forceinline__ void cp16(void* s, const void* g) {
    unsigned sa = (unsigned)__cvta_generic_to_shared(s);
    asm volatile("cp.async.cg.shared.global [%0], [%1], 16;\n" :: "r"(sa), "l"(g));
}
__device__ __forceinline__ void cp_commit() { asm volatile("cp.async.commit_group;\n"); }
__device__ __forceinline__ void cp_wait1()  { asm volatile("cp.async.wait_group 1;\n"); }

__device__ __forceinline__ float leakyf(float x) { return fmaxf(x, ALPHA * x); }

__device__ __forceinline__ float pcalc(int aj, float e, float m) {
    float x = leakyf(e);
    return aj ? __expf(x - m) : 0.f;
}

// ---------------- kernel 1: Wh = h@W (fp32), write WhT fp16, es, ed ----------
__global__ void __launch_bounds__(256) k_wh(const float* __restrict__ h,
                                            const float* __restrict__ Wm,
                                            const float* __restrict__ a) {
    // phase-1 union: sW[32][128] (16384B) + sH[64][33] (8448B) = 24832B
    // phase-2:       sWh[64][132]                              = 33792B
    __shared__ __align__(16) char sbuf[64 * 132 * 4];
    __shared__ float sWa1[F_DIM], sWa2[F_DIM];

    float (*sW)[128] = reinterpret_cast<float(*)[128]>(sbuf);
    float (*sH)[33]  = reinterpret_cast<float(*)[33]>(sbuf + 16384);
    float (*sWh)[132] = reinterpret_cast<float(*)[132]>(sbuf);

    const int t  = threadIdx.x;
    const int tx = t & 31;
    const int ty = t >> 5;
    const int i0 = blockIdx.x * 64;

    if (t < F_DIM) { sWa1[t] = a[t]; sWa2[t] = a[F_DIM + t]; }

    float acc[8][4];
#pragma unroll
    for (int r = 0; r < 8; ++r)
#pragma unroll
        for (int c = 0; c < 4; ++c) acc[r][c] = 0.f;

    for (int kb = 0; kb < 4; ++kb) {
        const int k0 = kb * 32;
        __syncthreads();
        // W tile: 32 x 128
#pragma unroll
        for (int m = 0; m < 16; ++m) {
            int idx = t + m * 256;
            int r = idx >> 7, c = idx & 127;
            sW[r][c] = Wm[(k0 + r) * F_DIM + c];
        }
        // h tile: 64 x 32
#pragma unroll
        for (int m = 0; m < 8; ++m) {
            int idx = t + m * 256;
            int r = idx >> 5, c = idx & 31;
            sH[r][c] = h[(size_t)(i0 + r) * F_DIM + k0 + c];
        }
        __syncthreads();
#pragma unroll 4
        for (int kk = 0; kk < 32; ++kk) {
            float4 bv = *(const float4*)&sW[kk][tx * 4];
#pragma unroll
            for (int rr = 0; rr < 8; ++rr) {
                float av = sH[ty * 8 + rr][kk];
                acc[rr][0] += av * bv.x;
                acc[rr][1] += av * bv.y;
                acc[rr][2] += av * bv.z;
                acc[rr][3] += av * bv.w;
            }
        }
    }
    __syncthreads();
#pragma unroll
    for (int rr = 0; rr < 8; ++rr) {
        *(float4*)&sWh[ty * 8 + rr][tx * 4] =
            make_float4(acc[rr][0], acc[rr][1], acc[rr][2], acc[rr][3]);
    }
    __syncthreads();

    // es / ed : warp ty owns rows ty*8 .. ty*8+7  (dot Wh row with a1 / a2)
#pragma unroll
    for (int rr = 0; rr < 8; ++rr) {
        int r = ty * 8 + rr;
        float4 v = *(const float4*)&sWh[r][tx * 4];
        float s1 = v.x * sWa1[tx * 4] + v.y * sWa1[tx * 4 + 1] +
                   v.z * sWa1[tx * 4 + 2] + v.w * sWa1[tx * 4 + 3];
        float s2 = v.x * sWa2[tx * 4] + v.y * sWa2[tx * 4 + 1] +
                   v.z * sWa2[tx * 4 + 2] + v.w * sWa2[tx * 4 + 3];
#pragma unroll
        for (int off = 16; off; off >>= 1) {
            s1 += __shfl_xor_sync(0xffffffffu, s1, off);
            s2 += __shfl_xor_sync(0xffffffffu, s2, off);
        }
        if (tx == 0) { g_es[i0 + r] = s1; g_ed[i0 + r] = s2; }
    }

    // WhT fp16: thread t -> feature c = t/2, rows (t&1)*32 .. +31
    {
        int c = t >> 1, roff = (t & 1) * 32;
#pragma unroll 8
        for (int i = 0; i < 32; ++i) {
            int r = roff + i;
            g_WhT[(size_t)c * N_NODES + i0 + r] = __float2half(sWh[r][c]);
        }
    }
}

// ---------------- kernel 2: global max of ed ---------------------------------
__global__ void k_max() {
    __shared__ float red[256];
    int t = threadIdx.x;
    float m = -1e30f;
    for (int i = t; i < N_NODES; i += 256) m = fmaxf(m, g_ed[i]);
    red[t] = m;
    __syncthreads();
#pragma unroll
    for (int s = 128; s; s >>= 1) {
        if (t < s) red[t] = fmaxf(red[t], red[t + s]);
        __syncthreads();
    }
    if (t == 0) g_maxed = red[0];
}

// ---------------- kernel 3: fused masked-softmax attention @ Wh --------------
// grid: 128 CTAs (64 rows each), 256 threads (8 warps: 4 row-groups x 2 K-halves)
#define BM 64
#define BN 128
#define NJ (N_NODES / BN)
#define ADJ_PB 544           // bytes/row  (136 ints)
#define WHT_PH 136           // halfs/row  (272 bytes)
#define ADJ_TILE (64 * ADJ_PB)      // 34816
#define WHT_TILE (128 * WHT_PH * 2) // 34816
#define OFF_A0 0
#define OFF_A1 (OFF_A0 + ADJ_TILE)
#define OFF_W0 (OFF_A1 + ADJ_TILE)
#define OFF_W1 (OFF_W0 + WHT_TILE)
#define OFF_E0 (OFF_W1 + WHT_TILE)
#define OFF_E1 (OFF_E0 + 512)
#define SMEM_FLASH (OFF_E1 + 512)   // 140288

__global__ void __launch_bounds__(256, 1) k_flash(const int* __restrict__ adj,
                                                  float* __restrict__ out) {
    extern __shared__ __align__(16) char sm[];
    const int t = threadIdx.x;
    const int l = t & 31;
    const int w = t >> 5;
    const int rg = w & 3;    // row group (16 rows)
    const int kh = w >> 2;   // K half (j cols kh*64 .. +63 of tile)
    const int i0 = blockIdx.x * BM;

    const int row0 = rg * 16 + (l >> 2);
    const int row1 = row0 + 8;

    const float maxed = g_maxed;
    const float es0 = g_es[i0 + row0];
    const float es1 = g_es[i0 + row1];
    const float m0 = leakyf(es0 + maxed);
    const float m1 = leakyf(es1 + maxed);

    float acc[16][4];
#pragma unroll
    for (int n = 0; n < 16; ++n)
#pragma unroll
        for (int i = 0; i < 4; ++i) acc[n][i] = 0.f;
    float ls0 = 0.f, ls1 = 0.f;

    // ---- async tile loader ----
    auto issue = [&](int buf, int jb) {
        const int j0 = jb * BN;
        char* A  = sm + (buf ? OFF_A1 : OFF_A0);
        char* Wt = sm + (buf ? OFF_W1 : OFF_W0);
        char* E  = sm + (buf ? OFF_E1 : OFF_E0);
#pragma unroll
        for (int m = 0; m < 8; ++m) {               // adj 64 x 128 ints
            int c = t + m * 256;
            int r = c >> 5, cc = c & 31;
            cp16(A + r * ADJ_PB + cc * 16, adj + (size_t)(i0 + r) * N_NODES + j0 + cc * 4);
        }
#pragma unroll
        for (int m = 0; m < 8; ++m) {               // WhT 128 x 128 halfs
            int c = t + m * 256;
            int r = c >> 4, cc = c & 15;
            cp16(Wt + r * (WHT_PH * 2) + cc * 16, g_WhT + (size_t)r * N_NODES + j0 + cc * 8);
        }
        if (t < 32) cp16(E + t * 16, g_ed + j0 + t * 4);   // ed tile (128 f32)
    };

    issue(0, 0);
    cp_commit();

    for (int jb = 0; jb < NJ; ++jb) {
        const int buf = jb & 1;
        __syncthreads();                 // prev compute done before refilling buf^1
        if (jb + 1 < NJ) issue(buf ^ 1, jb + 1);
        cp_commit();
        cp_wait1();
        __syncthreads();

        const char*  A  = sm + (buf ? OFF_A1 : OFF_A0);
        const __half* Wt = (const __half*)(sm + (buf ? OFF_W1 : OFF_W0));
        const float* E  = (const float*)(sm + (buf ? OFF_E1 : OFF_E0));
        const int* ar0 = (const int*)(A + row0 * ADJ_PB);
        const int* ar1 = (const int*)(A + row1 * ADJ_PB);

#pragma unroll
        for (int ktl = 0; ktl < 4; ++ktl) {
            const int c0 = kh * 64 + ktl * 16 + (l & 3) * 2;
            float e0 = E[c0], e1 = E[c0 + 1], e8 = E[c0 + 8], e9 = E[c0 + 9];
            int2 q00 = *(const int2*)&ar0[c0];
            int2 q08 = *(const int2*)&ar0[c0 + 8];
            int2 q10 = *(const int2*)&ar1[c0];
            int2 q18 = *(const int2*)&ar1[c0 + 8];

            float p00 = pcalc(q00.x, es0 + e0, m0);
            float p01 = pcalc(q00.y, es0 + e1, m0);
            float p08 = pcalc(q08.x, es0 + e8, m0);
            float p09 = pcalc(q08.y, es0 + e9, m0);
            float p10 = pcalc(q10.x, es1 + e0, m1);
            float p11 = pcalc(q10.y, es1 + e1, m1);
            float p18 = pcalc(q18.x, es1 + e8, m1);
            float p19 = pcalc(q18.y, es1 + e9, m1);

            ls0 += (p00 + p01) + (p08 + p09);
            ls1 += (p10 + p11) + (p18 + p19);

            uint32_t a0 = packh2(p00, p01);
            uint32_t a1 = packh2(p10, p11);
            uint32_t a2 = packh2(p08, p09);
            uint32_t a3 = packh2(p18, p19);

            const __half* bbase = Wt + (size_t)(l >> 2) * WHT_PH + c0;
#pragma unroll
            for (int nt = 0; nt < 16; ++nt) {
                const __half* bp = bbase + nt * 8 * WHT_PH;
                uint32_t b0 = *(const uint32_t*)bp;
                uint32_t b1 = *(const uint32_t*)(bp + 8);
                mma16816(acc[nt], a0, a1, a2, a3, b0, b1);
            }
        }
    }

    // quad-reduce row sums (lanes sharing l>>2)
    ls0 += __shfl_xor_sync(0xffffffffu, ls0, 1);
    ls0 += __shfl_xor_sync(0xffffffffu, ls0, 2);
    ls1 += __shfl_xor_sync(0xffffffffu, ls1, 1);
    ls1 += __shfl_xor_sync(0xffffffffu, ls1, 2);

    __syncthreads();
    float* mrg  = (float*)sm;                 // 4 warps * 2048 f = 32KB (in adj area)
    float* mrgL = (float*)(sm + OFF_E0);      // 512B

    if (kh == 1) {
#pragma unroll
        for (int nt = 0; nt < 16; ++nt)
            *(float4*)&mrg[rg * 2048 + nt * 128 + l * 4] =
                make_float4(acc[nt][0], acc[nt][1], acc[nt][2], acc[nt][3]);
        if ((l & 3) == 0) {
            mrgL[rg * 32 + (l >> 2) * 2]     = ls0;
            mrgL[rg * 32 + (l >> 2) * 2 + 1] = ls1;
        }
    }
    __syncthreads();
    if (kh == 0) {
        ls0 += mrgL[rg * 32 + (l >> 2) * 2];
        ls1 += mrgL[rg * 32 + (l >> 2) * 2 + 1];
        float inv0 = 1.f / ls0;
        float inv1 = 1.f / ls1;
#pragma unroll
        for (int nt = 0; nt < 16; ++nt) {
            float4 p = *(const float4*)&mrg[rg * 2048 + nt * 128 + l * 4];
            float o0 = (acc[nt][0] + p.x) * inv0;
            float o1 = (acc[nt][1] + p.y) * inv0;
            float o2 = (acc[nt][2] + p.z) * inv1;
            float o3 = (acc[nt][3] + p.w) * inv1;
            int col = nt * 8 + (l & 3) * 2;
            *(float2*)&out[(size_t)(i0 + row0) * F_DIM + col] = make_float2(o0, o1);
            *(float2*)&out[(size_t)(i0 + row1) * F_DIM + col] = make_float2(o2, o3);
        }
    }
}

// ---------------- launcher ---------------------------------------------------
extern "C" void kernel_launch(void* const* d_in, const int* in_sizes, int n_in,
                              void* d_out, int out_size) {
    const float* h   = (const float*)d_in[0];
    const int*   adj = (const int*)d_in[1];
    const float* W   = (const float*)d_in[2];
    const float* a   = (const float*)d_in[3];
    float* out = (float*)d_out;

    k_wh<<<N_NODES / 64, 256>>>(h, W, a);
    k_max<<<1, 256>>>();

    cudaFuncSetAttribute(k_flash, cudaFuncAttributeMaxDynamicSharedMemorySize, SMEM_FLASH);
    k_flash<<<N_NODES / BM, 256, SMEM_FLASH>>>(adj, out);
}

// round 5
// speedup vs baseline: 1.2713x; 1.2607x over previous
#include <cuda_runtime.h>
#include <cuda_fp16.h>
#include <cstdint>

#define N_NODES 8192
#define F_DIM   128
#define ALPHA   0.2f

__device__ float  g_es[N_NODES];
__device__ float  g_ed[N_NODES];
__device__ __half g_WhT[(size_t)F_DIM * N_NODES];   // [f][node]

__device__ __forceinline__ uint32_t packh2(float x, float y) {
    __half2 h = __floats2half2_rn(x, y);
    return reinterpret_cast<uint32_t&>(h);
}
__device__ __forceinline__ void mma16816(float* c,
                                         uint32_t a0, uint32_t a1, uint32_t a2, uint32_t a3,
                                         uint32_t b0, uint32_t b1) {
    asm volatile(
        "mma.sync.aligned.m16n8k16.row.col.f32.f16.f16.f32 "
        "{%0,%1,%2,%3}, {%4,%5,%6,%7}, {%8,%9}, {%0,%1,%2,%3};\n"
        : "+f"(c[0]), "+f"(c[1]), "+f"(c[2]), "+f"(c[3])
        : "r"(a0), "r"(a1), "r"(a2), "r"(a3), "r"(b0), "r"(b1));
}
__device__ __forceinline__ void cp16(void* s, const void* g) {
    unsigned sa = (unsigned)__cvta_generic_to_shared(s);
    asm volatile("cp.async.cg.shared.global [%0], [%1], 16;\n" :: "r"(sa), "l"(g));
}
__device__ __forceinline__ void cp_commit() { asm volatile("cp.async.commit_group;\n"); }
__device__ __forceinline__ void cp_wait1()  { asm volatile("cp.async.wait_group 1;\n"); }
__device__ __forceinline__ float leakyf(float x) { return fmaxf(x, ALPHA * x); }
__device__ __forceinline__ float pcalc(int aj, float e, float m) {
    float x = leakyf(e);
    return aj ? __expf(x - m) : 0.f;
}

// ---------------- kernel 1: Wh = h@W (fp32), WhT fp16, es, ed ----------------
__global__ void __launch_bounds__(256) k_wh(const float* __restrict__ h,
                                            const float* __restrict__ Wm,
                                            const float* __restrict__ a) {
    __shared__ __align__(16) char sbuf[64 * 132 * 4];
    __shared__ float sWa1[F_DIM], sWa2[F_DIM];
    float (*sW)[128]  = reinterpret_cast<float(*)[128]>(sbuf);
    float (*sH)[33]   = reinterpret_cast<float(*)[33]>(sbuf + 16384);
    float (*sWh)[132] = reinterpret_cast<float(*)[132]>(sbuf);

    const int t = threadIdx.x, tx = t & 31, ty = t >> 5;
    const int i0 = blockIdx.x * 64;
    if (t < F_DIM) { sWa1[t] = a[t]; sWa2[t] = a[F_DIM + t]; }

    float acc[8][4];
#pragma unroll
    for (int r = 0; r < 8; ++r)
#pragma unroll
        for (int c = 0; c < 4; ++c) acc[r][c] = 0.f;

    for (int kb = 0; kb < 4; ++kb) {
        const int k0 = kb * 32;
        __syncthreads();
#pragma unroll
        for (int m = 0; m < 16; ++m) {
            int idx = t + m * 256, r = idx >> 7, c = idx & 127;
            sW[r][c] = Wm[(k0 + r) * F_DIM + c];
        }
#pragma unroll
        for (int m = 0; m < 8; ++m) {
            int idx = t + m * 256, r = idx >> 5, c = idx & 31;
            sH[r][c] = h[(size_t)(i0 + r) * F_DIM + k0 + c];
        }
        __syncthreads();
#pragma unroll 4
        for (int kk = 0; kk < 32; ++kk) {
            float4 bv = *(const float4*)&sW[kk][tx * 4];
#pragma unroll
            for (int rr = 0; rr < 8; ++rr) {
                float av = sH[ty * 8 + rr][kk];
                acc[rr][0] += av * bv.x; acc[rr][1] += av * bv.y;
                acc[rr][2] += av * bv.z; acc[rr][3] += av * bv.w;
            }
        }
    }
    __syncthreads();
#pragma unroll
    for (int rr = 0; rr < 8; ++rr)
        *(float4*)&sWh[ty * 8 + rr][tx * 4] =
            make_float4(acc[rr][0], acc[rr][1], acc[rr][2], acc[rr][3]);
    __syncthreads();

#pragma unroll
    for (int rr = 0; rr < 8; ++rr) {
        int r = ty * 8 + rr;
        float4 v = *(const float4*)&sWh[r][tx * 4];
        float s1 = v.x * sWa1[tx*4] + v.y * sWa1[tx*4+1] + v.z * sWa1[tx*4+2] + v.w * sWa1[tx*4+3];
        float s2 = v.x * sWa2[tx*4] + v.y * sWa2[tx*4+1] + v.z * sWa2[tx*4+2] + v.w * sWa2[tx*4+3];
#pragma unroll
        for (int off = 16; off; off >>= 1) {
            s1 += __shfl_xor_sync(0xffffffffu, s1, off);
            s2 += __shfl_xor_sync(0xffffffffu, s2, off);
        }
        if (tx == 0) { g_es[i0 + r] = s1; g_ed[i0 + r] = s2; }
    }
    {
        int c = t >> 1, roff = (t & 1) * 32;
#pragma unroll 8
        for (int i = 0; i < 32; ++i)
            g_WhT[(size_t)c * N_NODES + i0 + roff + i] = __float2half(sWh[roff + i][c]);
    }
}

// ---------------- kernel 2: fused masked-softmax attention @ Wh --------------
// 128 CTAs x 64 rows, 512 threads: 16 warps = 4 row-groups x 4 K-quarters
#define BM 64
#define BN 128
#define NJ (N_NODES / BN)
#define ADJ_PB 544
#define WHT_PH 136
#define ADJ_TILE (64 * ADJ_PB)
#define WHT_TILE (128 * WHT_PH * 2)
#define OFF_A0 0
#define OFF_A1 (OFF_A0 + ADJ_TILE)
#define OFF_W0 (OFF_A1 + ADJ_TILE)
#define OFF_W1 (OFF_W0 + WHT_TILE)
#define OFF_E0 (OFF_W1 + WHT_TILE)
#define OFF_E1 (OFF_E0 + 512)
#define OFF_LS (OFF_E1 + 512)
#define SMEM_FLASH (OFF_LS + 2112)

__global__ void __launch_bounds__(512, 1) k_flash(const int* __restrict__ adj,
                                                  float* __restrict__ out) {
    extern __shared__ __align__(16) char sm[];
    const int t = threadIdx.x, l = t & 31, w = t >> 5;
    const int rg = w & 3;          // 16-row group
    const int kq = w >> 2;         // 32-col quarter of the j-tile
    const int i0 = blockIdx.x * BM;
    const int row0 = rg * 16 + (l >> 2);
    const int row1 = row0 + 8;
    float* lsbuf = (float*)(sm + OFF_LS);

    auto issue = [&](int buf, int jb) {
        const int j0 = jb * BN;
        char* A  = sm + (buf ? OFF_A1 : OFF_A0);
        char* Wt = sm + (buf ? OFF_W1 : OFF_W0);
        char* E  = sm + (buf ? OFF_E1 : OFF_E0);
#pragma unroll
        for (int m = 0; m < 4; ++m) {
            int c = t + m * 512, r = c >> 5, cc = c & 31;
            cp16(A + r * ADJ_PB + cc * 16, adj + (size_t)(i0 + r) * N_NODES + j0 + cc * 4);
        }
#pragma unroll
        for (int m = 0; m < 4; ++m) {
            int c = t + m * 512, r = c >> 4, cc = c & 15;
            cp16(Wt + r * (WHT_PH * 2) + cc * 16, g_WhT + (size_t)r * N_NODES + j0 + cc * 8);
        }
        if (t < 32) cp16(E + t * 16, g_ed + j0 + t * 4);
    };

    issue(0, 0);
    cp_commit();

    // global max of ed (overlapped with first tile's cp.async)
    float mx = -1e30f;
    for (int i = t; i < N_NODES; i += 512) mx = fmaxf(mx, g_ed[i]);
#pragma unroll
    for (int o = 16; o; o >>= 1) mx = fmaxf(mx, __shfl_xor_sync(0xffffffffu, mx, o));
    if (l == 0) lsbuf[w] = mx;
    __syncthreads();
    if (t == 0) {
        float m2 = lsbuf[0];
        for (int i = 1; i < 16; ++i) m2 = fmaxf(m2, lsbuf[i]);
        lsbuf[16] = m2;
    }
    __syncthreads();
    const float maxed = lsbuf[16];

    const float es0 = g_es[i0 + row0];
    const float es1 = g_es[i0 + row1];
    const float m0 = leakyf(es0 + maxed);
    const float m1 = leakyf(es1 + maxed);

    float acc[16][4];
#pragma unroll
    for (int n = 0; n < 16; ++n)
#pragma unroll
        for (int i = 0; i < 4; ++i) acc[n][i] = 0.f;
    float ls0 = 0.f, ls1 = 0.f;

    for (int jb = 0; jb < NJ; ++jb) {
        const int buf = jb & 1;
        __syncthreads();
        if (jb + 1 < NJ) issue(buf ^ 1, jb + 1);
        cp_commit();
        cp_wait1();
        __syncthreads();

        const char*   A  = sm + (buf ? OFF_A1 : OFF_A0);
        const __half* Wt = (const __half*)(sm + (buf ? OFF_W1 : OFF_W0));
        const float*  E  = (const float*)(sm + (buf ? OFF_E1 : OFF_E0));
        const int* ar0 = (const int*)(A + row0 * ADJ_PB);
        const int* ar1 = (const int*)(A + row1 * ADJ_PB);

#pragma unroll
        for (int ktl = 0; ktl < 2; ++ktl) {
            const int c0 = kq * 32 + ktl * 16 + (l & 3) * 2;
            float e0 = E[c0], e1 = E[c0 + 1], e8 = E[c0 + 8], e9 = E[c0 + 9];
            int2 q00 = *(const int2*)&ar0[c0];
            int2 q08 = *(const int2*)&ar0[c0 + 8];
            int2 q10 = *(const int2*)&ar1[c0];
            int2 q18 = *(const int2*)&ar1[c0 + 8];

            float p00 = pcalc(q00.x, es0 + e0, m0);
            float p01 = pcalc(q00.y, es0 + e1, m0);
            float p08 = pcalc(q08.x, es0 + e8, m0);
            float p09 = pcalc(q08.y, es0 + e9, m0);
            float p10 = pcalc(q10.x, es1 + e0, m1);
            float p11 = pcalc(q10.y, es1 + e1, m1);
            float p18 = pcalc(q18.x, es1 + e8, m1);
            float p19 = pcalc(q18.y, es1 + e9, m1);

            ls0 += (p00 + p01) + (p08 + p09);
            ls1 += (p10 + p11) + (p18 + p19);

            uint32_t a0 = packh2(p00, p01);
            uint32_t a1 = packh2(p10, p11);
            uint32_t a2 = packh2(p08, p09);
            uint32_t a3 = packh2(p18, p19);

            const __half* bbase = Wt + (size_t)(l >> 2) * WHT_PH + c0;
#pragma unroll
            for (int nt = 0; nt < 16; ++nt) {
                const __half* bp = bbase + nt * 8 * WHT_PH;
                uint32_t b0 = *(const uint32_t*)bp;
                uint32_t b1 = *(const uint32_t*)(bp + 8);
                mma16816(acc[nt], a0, a1, a2, a3, b0, b1);
            }
        }
    }

    // quad reduce row sums
    ls0 += __shfl_xor_sync(0xffffffffu, ls0, 1);
    ls0 += __shfl_xor_sync(0xffffffffu, ls0, 2);
    ls1 += __shfl_xor_sync(0xffffffffu, ls1, 1);
    ls1 += __shfl_xor_sync(0xffffffffu, ls1, 2);

    float* mrg = (float*)sm;   // stage regions: q*8192 + rg*2048 + nt*128 + l*4
    __syncthreads();
    if (kq > 0 && (l & 3) == 0) {
        lsbuf[kq * 128 + rg * 32 + (l >> 2) * 2]     = ls0;
        lsbuf[kq * 128 + rg * 32 + (l >> 2) * 2 + 1] = ls1;
    }
    if (kq >= 2) {
#pragma unroll
        for (int nt = 0; nt < 16; ++nt)
            *(float4*)&mrg[(kq - 2) * 8192 + rg * 2048 + nt * 128 + l * 4] =
                make_float4(acc[nt][0], acc[nt][1], acc[nt][2], acc[nt][3]);
    }
    __syncthreads();
    if (kq < 2) {
#pragma unroll
        for (int nt = 0; nt < 16; ++nt) {
            float4 p = *(const float4*)&mrg[kq * 8192 + rg * 2048 + nt * 128 + l * 4];
            acc[nt][0] += p.x; acc[nt][1] += p.y; acc[nt][2] += p.z; acc[nt][3] += p.w;
        }
    }
    if (kq == 0) {
        int b = rg * 32 + (l >> 2) * 2;
        ls0 += lsbuf[128 + b] + lsbuf[256 + b] + lsbuf[384 + b];
        ls1 += lsbuf[128 + b + 1] + lsbuf[256 + b + 1] + lsbuf[384 + b + 1];
    }
    __syncthreads();
    if (kq == 1) {
#pragma unroll
        for (int nt = 0; nt < 16; ++nt)
            *(float4*)&mrg[rg * 2048 + nt * 128 + l * 4] =
                make_float4(acc[nt][0], acc[nt][1], acc[nt][2], acc[nt][3]);
    }
    __syncthreads();
    if (kq == 0) {
        float inv0 = 1.f / ls0;
        float inv1 = 1.f / ls1;
#pragma unroll
        for (int nt = 0; nt < 16; ++nt) {
            float4 p = *(const float4*)&mrg[rg * 2048 + nt * 128 + l * 4];
            float o0 = (acc[nt][0] + p.x) * inv0;
            float o1 = (acc[nt][1] + p.y) * inv0;
            float o2 = (acc[nt][2] + p.z) * inv1;
            float o3 = (acc[nt][3] + p.w) * inv1;
            int col = nt * 8 + (l & 3) * 2;
            *(float2*)&out[(size_t)(i0 + row0) * F_DIM + col] = make_float2(o0, o1);
            *(float2*)&out[(size_t)(i0 + row1) * F_DIM + col] = make_float2(o2, o3);
        }
    }
}

// ---------------- launcher ---------------------------------------------------
extern "C" void kernel_launch(void* const* d_in, const int* in_sizes, int n_in,
                              void* d_out, int out_size) {
    const float* h   = (const float*)d_in[0];
    const int*   adj = (const int*)d_in[1];
    const float* W   = (const float*)d_in[2];
    const float* a   = (const float*)d_in[3];
    float* out = (float*)d_out;

    k_wh<<<N_NODES / 64, 256>>>(h, W, a);
    cudaFuncSetAttribute(k_flash, cudaFuncAttributeMaxDynamicSharedMemorySize, SMEM_FLASH);
    k_flash<<<N_NODES / BM, 512, SMEM_FLASH>>>(adj, out);
}